// round 3
// baseline (speedup 1.0000x reference)
#include <cuda_runtime.h>
#include <cstdint>

// Problem constants (fixed by the dataset)
#define BB     2048
#define NN     512
#define XX     32
#define HH     64

#define THREADS 256
#define BC      16     // batches per CTA
#define RR      4      // batches per thread
#define PP      2      // f32x2 pairs per thread
#define KTOT    96     // 64 h-rows + 32 x-rows
#define VSTR    18     // padded column stride of the state buffer (floats)

static constexpr int W4_ELEMS = KTOT * HH * 4;          // 24576 floats
static constexpr int V_ELEMS  = KTOT * VSTR;            // 1728 floats per buffer
static constexpr int SMEM_BYTES = (W4_ELEMS + 2 * V_ELEMS) * 4;  // 112128 B

__device__ __forceinline__ uint64_t pack2(float lo, float hi) {
    uint64_t r;
    asm("mov.b64 %0, {%1, %2};" : "=l"(r) : "f"(lo), "f"(hi));
    return r;
}
__device__ __forceinline__ void unpack2(uint64_t v, float& lo, float& hi) {
    asm("mov.b64 {%0, %1}, %2;" : "=f"(lo), "=f"(hi) : "l"(v));
}
__device__ __forceinline__ uint64_t ffma2(uint64_t a, uint64_t b, uint64_t c) {
    uint64_t d;
    asm("fma.rn.f32x2 %0, %1, %2, %3;" : "=l"(d) : "l"(a), "l"(b), "l"(c));
    return d;
}

__device__ __forceinline__ float sigm_fast(float z) {
    return __fdividef(1.0f, 1.0f + __expf(-z));
}
// tanh(z) = 2/(1+exp(-2z)) - 1 : safe for exp overflow in either direction
__device__ __forceinline__ float tanh_fast(float z) {
    float t = __expf(-2.0f * z);
    return 2.0f * __fdividef(1.0f, 1.0f + t) - 1.0f;
}

__global__ void __launch_bounds__(THREADS, 1)
lstm_scan_kernel(const float* __restrict__ x,
                 const float* __restrict__ ig_w_c, const float* __restrict__ ig_w_h,
                 const float* __restrict__ ig_w_x, const float* __restrict__ ig_b,
                 const float* __restrict__ fg_w_c, const float* __restrict__ fg_w_h,
                 const float* __restrict__ fg_w_x, const float* __restrict__ fg_b,
                 const float* __restrict__ in_w_h, const float* __restrict__ in_w_x,
                 const float* __restrict__ in_b,
                 const float* __restrict__ og_w_cn, const float* __restrict__ og_w_h,
                 const float* __restrict__ og_w_x, const float* __restrict__ og_b,
                 float* __restrict__ out)
{
    extern __shared__ float smem[];
    float* w4   = smem;                 // [k][u][gate] : (k*64+u)*4+g
    float* vbuf = smem + W4_ELEMS;      // [2][KTOT][VSTR]

    const int tid  = threadIdx.x;
    const int u    = tid & 63;          // hidden unit
    const int bg   = tid >> 6;          // batch group 0..3
    const int b0   = blockIdx.x * BC;   // global batch base of CTA
    const int col0 = bg * RR;           // local batch base of this thread

    // ---------------- prologue: weights -> shared (transposed, gate-packed) --
    {
        const float* wh[4] = {ig_w_h, fg_w_h, in_w_h, og_w_h};
        const float* wx[4] = {ig_w_x, fg_w_x, in_w_x, og_w_x};
        #pragma unroll
        for (int g = 0; g < 4; g++) {
            for (int idx = tid; idx < HH * HH; idx += THREADS) {
                int uu = idx >> 6, kk = idx & 63;           // source [u][k], k fastest -> coalesced
                w4[(kk * HH + uu) * 4 + g] = wh[g][idx];
            }
            for (int idx = tid; idx < HH * XX; idx += THREADS) {
                int uu = idx >> 5, kk = idx & 31;
                w4[((64 + kk) * HH + uu) * 4 + g] = wx[g][idx];
            }
        }
    }
    // zero h-rows of buffer 0
    for (int i = tid; i < 64 * VSTR; i += THREADS) vbuf[i] = 0.0f;

    // per-unit scalars
    const float wci  = ig_w_c[u];
    const float wcf  = fg_w_c[u];
    const float wocn = og_w_cn[u];
    const float bi   = ig_b[u];
    const float bf   = fg_b[u];
    const float bn   = in_b[u];
    const float bo   = og_b[u];

    // stage x_0 into buffer 0 (each thread: 2 consecutive elements of one batch row)
    const int e0  = tid * 2;            // e0 even -> k0 even -> same batch row for both
    const int bl0 = e0 >> 5;            // local batch of this thread's staging slot
    const int k0  = e0 & 31;
    {
        float2 xp = *reinterpret_cast<const float2*>(&x[(b0 + bl0) * NN * XX + k0]);
        vbuf[(64 + k0) * VSTR + bl0]     = xp.x;
        vbuf[(64 + k0 + 1) * VSTR + bl0] = xp.y;
    }
    __syncthreads();

    float c[RR];
    float hnew[RR];
    #pragma unroll
    for (int r = 0; r < RR; r++) c[r] = 0.0f;

    for (int t = 0; t < NN; t++) {
        const float* vcur = vbuf + (t & 1) * V_ELEMS;
        float*       vnxt = vbuf + ((t + 1) & 1) * V_ELEMS;

        // prefetch x_{t+1}
        float2 xp = make_float2(0.0f, 0.0f);
        if (t + 1 < NN) {
            xp = *reinterpret_cast<const float2*>(
                     &x[(b0 + bl0) * NN * XX + (t + 1) * XX + k0]);
        }

        // accumulators (biases folded in)
        uint64_t ai[PP], af[PP], an[PP], ao[PP];
        #pragma unroll
        for (int p = 0; p < PP; p++) {
            ai[p] = pack2(bi, bi);
            af[p] = pack2(bf, bf);
            an[p] = pack2(bn, bn);
            ao[p] = pack2(bo, bo);
        }

        // unified 96-deep dot: rows 0..63 are h, rows 64..95 are x_t
        #pragma unroll 8
        for (int k = 0; k < KTOT; k++) {
            float4 w = *reinterpret_cast<const float4*>(&w4[(k * HH + u) * 4]);
            uint64_t wi2 = pack2(w.x, w.x);
            uint64_t wf2 = pack2(w.y, w.y);
            uint64_t wn2 = pack2(w.z, w.z);
            uint64_t wo2 = pack2(w.w, w.w);
            #pragma unroll
            for (int p = 0; p < PP; p++) {
                uint64_t h2 = *reinterpret_cast<const uint64_t*>(
                                  &vcur[k * VSTR + col0 + 2 * p]);
                ai[p] = ffma2(wi2, h2, ai[p]);
                af[p] = ffma2(wf2, h2, af[p]);
                an[p] = ffma2(wn2, h2, an[p]);
                ao[p] = ffma2(wo2, h2, ao[p]);
            }
        }

        // finalize gates (scalar)
        float zi[RR], zf[RR], zn[RR], zo[RR];
        #pragma unroll
        for (int p = 0; p < PP; p++) {
            unpack2(ai[p], zi[2 * p], zi[2 * p + 1]);
            unpack2(af[p], zf[2 * p], zf[2 * p + 1]);
            unpack2(an[p], zn[2 * p], zn[2 * p + 1]);
            unpack2(ao[p], zo[2 * p], zo[2 * p + 1]);
        }
        #pragma unroll
        for (int r = 0; r < RR; r++) {
            float ig  = sigm_fast(zi[r] + wci * c[r]);
            float fg  = sigm_fast(zf[r] + wcf * c[r]);
            float inn = tanh_fast(zn[r]);
            float cn  = fg * c[r] + ig * inn;
            float og  = sigm_fast(zo[r] + wocn * cn);
            hnew[r]   = og * tanh_fast(cn);
            c[r]      = cn;
        }

        // publish h_{t+1} and x_{t+1} into the other buffer
        #pragma unroll
        for (int r = 0; r < RR; r++) vnxt[u * VSTR + col0 + r] = hnew[r];
        if (t + 1 < NN) {
            vnxt[(64 + k0) * VSTR + bl0]     = xp.x;
            vnxt[(64 + k0 + 1) * VSTR + bl0] = xp.y;
        }
        __syncthreads();
    }

    // final h -> out[B, H]
    #pragma unroll
    for (int r = 0; r < RR; r++) {
        out[(b0 + col0 + r) * HH + u] = hnew[r];
    }
}

extern "C" void kernel_launch(void* const* d_in, const int* in_sizes, int n_in,
                              void* d_out, int out_size)
{
    (void)in_sizes; (void)n_in; (void)out_size;
    const float* x       = (const float*)d_in[0];
    const float* ig_w_c  = (const float*)d_in[1];
    const float* ig_w_h  = (const float*)d_in[2];
    const float* ig_w_x  = (const float*)d_in[3];
    const float* ig_b    = (const float*)d_in[4];
    const float* fg_w_c  = (const float*)d_in[5];
    const float* fg_w_h  = (const float*)d_in[6];
    const float* fg_w_x  = (const float*)d_in[7];
    const float* fg_b    = (const float*)d_in[8];
    const float* in_w_h  = (const float*)d_in[9];
    const float* in_w_x  = (const float*)d_in[10];
    const float* in_b    = (const float*)d_in[11];
    const float* og_w_cn = (const float*)d_in[12];
    const float* og_w_h  = (const float*)d_in[13];
    const float* og_w_x  = (const float*)d_in[14];
    const float* og_b    = (const float*)d_in[15];
    float* out = (float*)d_out;

    cudaFuncSetAttribute(lstm_scan_kernel,
                         cudaFuncAttributeMaxDynamicSharedMemorySize, SMEM_BYTES);

    dim3 grid(BB / BC);   // 128 CTAs
    dim3 block(THREADS);
    lstm_scan_kernel<<<grid, block, SMEM_BYTES>>>(
        x, ig_w_c, ig_w_h, ig_w_x, ig_b,
        fg_w_c, fg_w_h, fg_w_x, fg_b,
        in_w_h, in_w_x, in_b,
        og_w_cn, og_w_h, og_w_x, og_b,
        out);
}